// round 14
// baseline (speedup 1.0000x reference)
#include <cuda_runtime.h>
#include <cuda_fp16.h>

typedef unsigned long long ull;
typedef unsigned int u32;

#define S_LEN  4096
#define HID    2048
#define NH_    16
#define NKV_   4
#define HD_    128
#define KD_KV  512
#define SCALE_ 0.08838834764831845f

// ---------------- scratch (static; no runtime alloc allowed) ----------------
__device__ __half g_hs16[(size_t)S_LEN * HID];
__device__ __half g_wq16[(size_t)HID   * HID];
__device__ __half g_wk16[(size_t)KD_KV * HID];
__device__ __half g_wv16[(size_t)KD_KV * HID];
__device__ __half g_wo16[(size_t)HID   * HID];
__device__ __half g_q16 [(size_t)S_LEN * HID];
__device__ __half g_k16 [(size_t)S_LEN * KD_KV];
__device__ __half g_v16 [(size_t)S_LEN * KD_KV];
__device__ __half g_ao16[(size_t)S_LEN * HID];

// ---------------- helpers ----------------
__device__ __forceinline__ u32 s2u(const void* p) {
    u32 a;
    asm("{ .reg .u64 t; cvta.to.shared.u64 t, %1; cvt.u32.u64 %0, t; }" : "=r"(a) : "l"(p));
    return a;
}
__device__ __forceinline__ u32 sw128(u32 o) { return o ^ ((o >> 3) & 0x70); }
__device__ __forceinline__ void cp16(u32 dst, const void* src) {
    asm volatile("cp.async.cg.shared.global [%0], [%1], 16;" :: "r"(dst), "l"(src));
}
__device__ __forceinline__ void cp_commit() { asm volatile("cp.async.commit_group;" ::: "memory"); }
template<int N> __device__ __forceinline__ void cp_wait() {
    asm volatile("cp.async.wait_group %0;" :: "n"(N) : "memory");
}

__device__ __forceinline__ void ldmx4(u32* r, u32 addr) {
    asm volatile("ldmatrix.sync.aligned.m8n8.x4.shared.b16 {%0,%1,%2,%3}, [%4];"
                 : "=r"(r[0]), "=r"(r[1]), "=r"(r[2]), "=r"(r[3]) : "r"(addr));
}
__device__ __forceinline__ void ldmx4t(u32* r, u32 addr) {
    asm volatile("ldmatrix.sync.aligned.m8n8.x4.trans.shared.b16 {%0,%1,%2,%3}, [%4];"
                 : "=r"(r[0]), "=r"(r[1]), "=r"(r[2]), "=r"(r[3]) : "r"(addr));
}
__device__ __forceinline__ void mma16816h(float* c, const u32* a, u32 b0, u32 b1) {
    asm volatile("mma.sync.aligned.m16n8k16.row.col.f32.f16.f16.f32 "
                 "{%0,%1,%2,%3}, {%4,%5,%6,%7}, {%8,%9}, {%0,%1,%2,%3};"
                 : "+f"(c[0]), "+f"(c[1]), "+f"(c[2]), "+f"(c[3])
                 : "r"(a[0]), "r"(a[1]), "r"(a[2]), "r"(a[3]), "r"(b0), "r"(b1));
}

// ---------------- fused fp32 -> fp16 conversion of all 5 inputs (2-way ILP) ------
// float4 units: hs [0,2097152) wq [..,3145728) wk [..,3407872) wv [..,3670016) wo [..,4718592)
#define CVT_N4   4718592
#define CVT_HALF 2359296
__device__ __forceinline__ void cvt_one(int i,
    const float* hs, const float* wq, const float* wk, const float* wv, const float* wo,
    __half* ohs, __half* owq, __half* owk, __half* owv, __half* owo)
{
    const float* src; __half* dst; int off;
    if (i < 2097152)      { src = hs; dst = ohs; off = i; }
    else if (i < 3145728) { src = wq; dst = owq; off = i - 2097152; }
    else if (i < 3407872) { src = wk; dst = owk; off = i - 3145728; }
    else if (i < 3670016) { src = wv; dst = owv; off = i - 3407872; }
    else                  { src = wo; dst = owo; off = i - 3670016; }
    float4 f = ((const float4*)src)[off];
    __half2 h0 = __floats2half2_rn(f.x, f.y);
    __half2 h1 = __floats2half2_rn(f.z, f.w);
    ((uint2*)dst)[off] = make_uint2(*(u32*)&h0, *(u32*)&h1);
}

__global__ __launch_bounds__(256)
void cvt_all(const float* __restrict__ hs, const float* __restrict__ wq,
             const float* __restrict__ wk, const float* __restrict__ wv,
             const float* __restrict__ wo,
             __half* __restrict__ ohs, __half* __restrict__ owq,
             __half* __restrict__ owk, __half* __restrict__ owv,
             __half* __restrict__ owo)
{
    int i = blockIdx.x * 256 + threadIdx.x;
    cvt_one(i,            hs, wq, wk, wv, wo, ohs, owq, owk, owv, owo);
    cvt_one(i + CVT_HALF, hs, wq, wk, wv, wo, ohs, owq, owk, owv, owo);
}

// ---------------- fp16 mma.sync GEMM core: 128(M) x 256(N) tile ----------------
// chunk = K64 fp16 (128B rows, SW128). 3 buffers, single-sync multistage.
// stage = A 16KB + B 32KB = 48KB
#define STAGEB 49152
#define NCHUNK 32
#define GEMM_SMEM (3 * STAGEB + 1024)

__device__ __forceinline__ void load_chunk(
    const __half* __restrict__ A, const __half* __restrict__ B,
    int bm, int c, u32 dstA, int tid)
{
    const int ko = c * 64;
    #pragma unroll
    for (int p = 0; p < 12; p++) {
        int u = tid + p * 256;                 // 0..3071 16B units
        if (u < 1024) {                        // A: 128 rows x 8 segs
            int row = u >> 3, seg = u & 7;
            u32 dst = dstA + sw128((u32)(row * 128 + seg * 16));
            cp16(dst, A + ((size_t)(bm + row)) * 2048 + ko + seg * 8);
        } else {                               // B: 256 rows x 8 segs
            int v = u - 1024;
            int row = v >> 3, seg = v & 7;
            u32 dst = dstA + 16384 + sw128((u32)(row * 128 + seg * 16));
            cp16(dst, B + ((size_t)row) * 2048 + ko + seg * 8);
        }
    }
    cp_commit();
}

template<bool OUT16>
__device__ __forceinline__ void gemm_core(
    const __half* __restrict__ A, const __half* __restrict__ B,
    void* __restrict__ Cv, int N, int bm, int bn, u32 sbase, int tid)
{
    const int wid = tid >> 5, L = tid & 31;
    const int wm = wid & 1, wn = wid >> 1;     // 2m x 4n warps; warp tile 64x64

    float acc[4][8][4];
    #pragma unroll
    for (int i = 0; i < 4; i++)
        #pragma unroll
        for (int j = 0; j < 8; j++)
            #pragma unroll
            for (int q2 = 0; q2 < 4; q2++) acc[i][j][q2] = 0.f;

    const u32 arow0 = (u32)(wm * 64 + (L & 15));
    const u32 a_sw  = (arow0 & 7) << 4;
    const u32 a_kl  = (u32)(L & 16);
    u32 brow[4], b_sw[4];
    const u32 b_kl = (u32)((L & 8) * 2);
    #pragma unroll
    for (int ng = 0; ng < 4; ng++) {
        brow[ng] = (u32)(wn * 64 + ng * 16 + (L & 7) + ((L & 16) >> 1));
        b_sw[ng] = (brow[ng] & 7) << 4;
    }

    // prologue: 2 stages ahead
    load_chunk(A, B, bm, 0, sbase + 0 * STAGEB, tid);
    load_chunk(A, B, bm, 1, sbase + 1 * STAGEB, tid);

    #pragma unroll 1
    for (int c = 0; c < NCHUNK; c++) {
        if (c + 1 < NCHUNK) cp_wait<1>();
        else                cp_wait<0>();
        __syncthreads();                        // stage c visible; all warps done with c-1
        if (c + 2 < NCHUNK)
            load_chunk(A, B, bm, c + 2, sbase + (u32)((c + 2) % 3) * STAGEB, tid);

        const u32 sA = sbase + (u32)(c % 3) * STAGEB;
        const u32 sB = sA + 16384;
        #pragma unroll
        for (int ks = 0; ks < 4; ks++) {
            const u32 kb2 = (u32)(ks * 32);
            u32 ar[4][4];
            u32 aad = sA + arow0 * 128 + ((kb2 + a_kl) ^ a_sw);
            #pragma unroll
            for (int mg = 0; mg < 4; mg++)
                ldmx4(ar[mg], aad + (u32)(mg * 2048));
            u32 br[16];
            #pragma unroll
            for (int ng = 0; ng < 4; ng++)
                ldmx4(br + ng * 4, sB + brow[ng] * 128 + ((kb2 + b_kl) ^ b_sw[ng]));
            #pragma unroll
            for (int mf = 0; mf < 4; mf++)
                #pragma unroll
                for (int nf = 0; nf < 8; nf++)
                    mma16816h(acc[mf][nf], ar[mf],
                              br[(nf >> 1) * 4 + (nf & 1) * 2],
                              br[(nf >> 1) * 4 + (nf & 1) * 2 + 1]);
        }
    }

    const int r0   = bm + wm * 64 + (L >> 2);
    const int col0 = bn + wn * 64 + (L & 3) * 2;
    #pragma unroll
    for (int mf = 0; mf < 4; mf++)
        #pragma unroll
        for (int nf = 0; nf < 8; nf++) {
            int r  = r0 + mf * 16;
            int cc = col0 + nf * 8;
            if (OUT16) {
                __half* C = (__half*)Cv;
                *(__half2*)&C[(size_t)r * N + cc] =
                    __floats2half2_rn(acc[mf][nf][0], acc[mf][nf][1]);
                *(__half2*)&C[(size_t)(r + 8) * N + cc] =
                    __floats2half2_rn(acc[mf][nf][2], acc[mf][nf][3]);
            } else {
                float* C = (float*)Cv;
                *(float2*)&C[(size_t)r * N + cc] =
                    make_float2(acc[mf][nf][0], acc[mf][nf][1]);
                *(float2*)&C[(size_t)(r + 8) * N + cc] =
                    make_float2(acc[mf][nf][2], acc[mf][nf][3]);
            }
        }
}

// merged QKV: grid.x = 12 n-tiles (8 q | 2 k | 2 v), grid.y = 32 m-tiles; fp16 out
__global__ __launch_bounds__(256)
void gemm_qkv(const __half* __restrict__ hs,
              const __half* __restrict__ wq, const __half* __restrict__ wk,
              const __half* __restrict__ wv,
              __half* __restrict__ q, __half* __restrict__ k, __half* __restrict__ v)
{
    extern __shared__ char smraw[];
    const u32 sbase = (s2u(smraw) + 1023) & ~1023u;
    const int nt = blockIdx.x, bm = blockIdx.y * 128;

    const __half* B; __half* C; int N, bn;
    if (nt < 8)       { B = wq + (size_t)nt * 256 * 2048;        C = q; N = HID;   bn = nt * 256; }
    else if (nt < 10) { B = wk + (size_t)(nt - 8) * 256 * 2048;  C = k; N = KD_KV; bn = (nt - 8) * 256; }
    else              { B = wv + (size_t)(nt - 10) * 256 * 2048; C = v; N = KD_KV; bn = (nt - 10) * 256; }

    gemm_core<true>(hs, B, C, N, bm, bn, sbase, threadIdx.x);
}

__global__ __launch_bounds__(256)
void gemm_wo(const __half* __restrict__ A, const __half* __restrict__ W,
             float* __restrict__ C)
{
    extern __shared__ char smraw[];
    const u32 sbase = (s2u(smraw) + 1023) & ~1023u;
    const int bn = blockIdx.x * 256, bm = blockIdx.y * 128;
    gemm_core<false>(A, W + (size_t)bn * 2048, C, HID, bm, bn, sbase, threadIdx.x);
}

// ---------------- merged RoPE on q + k (fp16 storage, fp32 math) ----------------
// slots 0..15 -> q heads, 16..19 -> k heads
__global__ __launch_bounds__(256)
void rope16_all(__half* __restrict__ q, __half* __restrict__ k,
                const float* __restrict__ cosb, const float* __restrict__ sinb)
{
    int idx = blockIdx.x * blockDim.x + threadIdx.x;
    int d  = idx & 63;
    int hslot = (idx >> 6) % 20;
    int s  = idx / (64 * 20);
    __half* p = (hslot < 16)
        ? q + (size_t)s * HID   + hslot * HD_
        : k + (size_t)s * KD_KV + (hslot - 16) * HD_;
    float x1 = __half2float(p[d]), x2 = __half2float(p[d + 64]);
    float c1 = cosb[s * HD_ + d],      s1 = sinb[s * HD_ + d];
    float c2 = cosb[s * HD_ + d + 64], s2 = sinb[s * HD_ + d + 64];
    p[d]      = __float2half(x1 * c1 - x2 * s1);
    p[d + 64] = __float2half(x2 * c2 + x1 * s2);
}

// ---------------- block-sparse attention: FA2-style, fp16 in/out ----------------
#define ATT_SMEM 81920

__device__ __forceinline__ void cp_row_tile(u32 dst, const __half* __restrict__ src,
                                            int rstride, int tid)
{
    #pragma unroll
    for (int p = 0; p < 8; p++) {
        int u = tid + p * 128;
        int r = u >> 4, seg = u & 15;
        u32 ad = dst + (u32)r * 256 + (((u32)(seg * 16)) ^ (((u32)r & 7) << 4));
        cp16(ad, src + (size_t)r * rstride + seg * 8);
    }
    cp_commit();
}

__global__ __launch_bounds__(128)
void attn_kernel(const __half* __restrict__ q, const __half* __restrict__ k,
                 const __half* __restrict__ v, __half* __restrict__ out)
{
    extern __shared__ char smc[];
    const u32 sb = s2u(smc);
    const u32 Qs = sb;
    const u32 Kb0 = sb + 16384, Kb1 = sb + 32768;
    const u32 Vb0 = sb + 49152, Vb1 = sb + 65536;

    const int t   = blockIdx.x;
    const int h   = blockIdx.y;
    const int kvh = h >> 2;
    const int tid = threadIdx.x;
    const int wid = tid >> 5, L = tid & 31;

    int sel[6]; int ns = 0;
    {
        int lo = t - 4; if (lo < 0) lo = 0;
        int g0 = ((t >> 2) << 2) - 4;
        if (g0 >= 0 && g0 < lo) sel[ns++] = g0;
        for (int b = lo; b <= t; b++) sel[ns++] = b;
    }

    cp_row_tile(Qs,  q + (size_t)(t * 64) * HID + h * HD_, HID, tid);
    cp_row_tile(Kb0, k + (size_t)(sel[0] * 64) * KD_KV + kvh * HD_, KD_KV, tid);
    cp_row_tile(Vb0, v + (size_t)(sel[0] * 64) * KD_KV + kvh * HD_, KD_KV, tid);

    const u32 arow = (u32)(wid * 16 + (L & 15));
    const u32 a_sw = (arow & 7) << 4;
    const u32 a_kl = (u32)(L & 16);
    u32 brow[4], b_sw[4];
    const u32 b_kl = (u32)((L & 8) * 2);
    #pragma unroll
    for (int g = 0; g < 4; g++) {
        brow[g] = (u32)(g * 16 + (L & 7) + ((L & 16) >> 1));
        b_sw[g] = (brow[g] & 7) << 4;
    }
    const u32 vrow = (u32)(L & 15);
    const u32 v_cl = (u32)((L >> 4) * 16);

    const int qrow = wid * 16 + (L >> 2);

    float o[16][4];
    #pragma unroll
    for (int nf = 0; nf < 16; nf++)
        #pragma unroll
        for (int j = 0; j < 4; j++) o[nf][j] = 0.f;
    float lp0 = 0.f, lp1 = 0.f;

    #pragma unroll 1
    for (int jb = 0; jb < ns; jb++) {
        const u32 Kc = (jb & 1) ? Kb1 : Kb0;
        const u32 Vc = (jb & 1) ? Vb1 : Vb0;

        if (jb + 1 < ns) {
            cp_row_tile((jb & 1) ? Kb0 : Kb1,
                        k + (size_t)(sel[jb + 1] * 64) * KD_KV + kvh * HD_, KD_KV, tid);
            cp_wait<2>();
        } else {
            cp_wait<1>();
        }
        __syncthreads();

        float cs[8][4];
        #pragma unroll
        for (int nf = 0; nf < 8; nf++)
            #pragma unroll
            for (int j = 0; j < 4; j++) cs[nf][j] = 0.f;

        #pragma unroll
        for (int ks = 0; ks < 8; ks++) {
            const u32 kb2 = (u32)(ks * 32);
            u32 ar[4];
            ldmx4(ar, Qs + arow * 256 + ((kb2 + a_kl) ^ a_sw));
            u32 br[16];
            #pragma unroll
            for (int g = 0; g < 4; g++)
                ldmx4(br + g * 4, Kc + brow[g] * 256 + ((kb2 + b_kl) ^ b_sw[g]));
            #pragma unroll
            for (int nf = 0; nf < 8; nf++)
                mma16816h(cs[nf], ar, br[(nf >> 1) * 4 + (nf & 1) * 2],
                                       br[(nf >> 1) * 4 + (nf & 1) * 2 + 1]);
        }

        const bool diag = (sel[jb] == t);
        u32 pf[4][4];
        #pragma unroll
        for (int nf = 0; nf < 8; nf++) {
            int colg = nf * 8 + (L & 3) * 2;
            float e0 = __expf(cs[nf][0] * SCALE_);
            float e1 = __expf(cs[nf][1] * SCALE_);
            float e2 = __expf(cs[nf][2] * SCALE_);
            float e3 = __expf(cs[nf][3] * SCALE_);
            if (diag) {
                if (colg     > qrow)     e0 = 0.f;
                if (colg + 1 > qrow)     e1 = 0.f;
                if (colg     > qrow + 8) e2 = 0.f;
                if (colg + 1 > qrow + 8) e3 = 0.f;
            }
            lp0 += e0 + e1;
            lp1 += e2 + e3;
            __half2 h01 = __floats2half2_rn(e0, e1);
            __half2 h23 = __floats2half2_rn(e2, e3);
            const int kf = nf >> 1;
            if ((nf & 1) == 0) { pf[kf][0] = *(u32*)&h01; pf[kf][1] = *(u32*)&h23; }
            else               { pf[kf][2] = *(u32*)&h01; pf[kf][3] = *(u32*)&h23; }
        }

        if (jb + 1 < ns) {
            cp_row_tile((jb & 1) ? Vb0 : Vb1,
                        v + (size_t)(sel[jb + 1] * 64) * KD_KV + kvh * HD_, KD_KV, tid);
            cp_wait<2>();
        } else {
            cp_wait<0>();
        }
        __syncthreads();

        #pragma unroll
        for (int kf = 0; kf < 4; kf++) {
            #pragma unroll
            for (int dg = 0; dg < 8; dg++) {
                u32 row = (u32)(kf * 16) + vrow;
                u32 cb  = (u32)(dg * 32) + v_cl;
                u32 vr[4];
                ldmx4t(vr, Vc + row * 256 + (cb ^ ((row & 7) << 4)));
                mma16816h(o[dg * 2 + 0], pf[kf], vr[0], vr[1]);
                mma16816h(o[dg * 2 + 1], pf[kf], vr[2], vr[3]);
            }
        }
    }

    lp0 += __shfl_xor_sync(0xFFFFFFFFu, lp0, 1);
    lp0 += __shfl_xor_sync(0xFFFFFFFFu, lp0, 2);
    lp1 += __shfl_xor_sync(0xFFFFFFFFu, lp1, 1);
    lp1 += __shfl_xor_sync(0xFFFFFFFFu, lp1, 2);
    const float il0 = 1.f / lp0, il1 = 1.f / lp1;

    #pragma unroll
    for (int nf = 0; nf < 16; nf++) {
        int col = nf * 8 + (L & 3) * 2;
        __half* o0 = out + (size_t)(t * 64 + qrow) * HID + h * HD_ + col;
        __half* o1 = out + (size_t)(t * 64 + qrow + 8) * HID + h * HD_ + col;
        *(__half2*)o0 = __floats2half2_rn(o[nf][0] * il0, o[nf][1] * il0);
        *(__half2*)o1 = __floats2half2_rn(o[nf][2] * il1, o[nf][3] * il1);
    }
}

// ---------------- launch ----------------
extern "C" void kernel_launch(void* const* d_in, const int* in_sizes, int n_in,
                              void* d_out, int out_size)
{
    const float* hs   = (const float*)d_in[0];
    const float* cosb = (const float*)d_in[1];
    const float* sinb = (const float*)d_in[2];
    const float* wq   = (const float*)d_in[3];
    const float* wk   = (const float*)d_in[4];
    const float* wv   = (const float*)d_in[5];
    const float* wo   = (const float*)d_in[6];
    float* out = (float*)d_out;

    __half *phs, *pwq, *pwk, *pwv, *pwo, *pq16, *pk16, *pv16, *pao16;
    cudaGetSymbolAddress((void**)&phs,   g_hs16);
    cudaGetSymbolAddress((void**)&pwq,   g_wq16);
    cudaGetSymbolAddress((void**)&pwk,   g_wk16);
    cudaGetSymbolAddress((void**)&pwv,   g_wv16);
    cudaGetSymbolAddress((void**)&pwo,   g_wo16);
    cudaGetSymbolAddress((void**)&pq16,  g_q16);
    cudaGetSymbolAddress((void**)&pk16,  g_k16);
    cudaGetSymbolAddress((void**)&pv16,  g_v16);
    cudaGetSymbolAddress((void**)&pao16, g_ao16);

    const dim3 blk(256);

    // fused fp32->fp16 conversion (2 units/thread)
    cvt_all<<<CVT_HALF / 256, blk>>>(hs, wq, wk, wv, wo, phs, pwq, pwk, pwv, pwo);

    cudaFuncSetAttribute(gemm_qkv, cudaFuncAttributeMaxDynamicSharedMemorySize, GEMM_SMEM);
    cudaFuncSetAttribute(gemm_wo,  cudaFuncAttributeMaxDynamicSharedMemorySize, GEMM_SMEM);

    // fused QKV projections -> fp16 (128x256 tiles)
    gemm_qkv<<<dim3(12, 32), blk, GEMM_SMEM>>>(phs, pwq, pwk, pwv, pq16, pk16, pv16);

    // merged RoPE on q + k
    rope16_all<<<(S_LEN * 20 * 64) / 256, blk>>>(pq16, pk16, cosb, sinb);

    // block-sparse attention (fp16 in/out)
    cudaFuncSetAttribute(attn_kernel,
                         cudaFuncAttributeMaxDynamicSharedMemorySize, ATT_SMEM);
    attn_kernel<<<dim3(64, NH_), dim3(128), ATT_SMEM>>>(pq16, pk16, pv16, pao16);

    // output projection (fp32 out, 128x256 tiles)
    gemm_wo<<<dim3(8, 32), blk, GEMM_SMEM>>>(pao16, pwo, out);
}

// round 15
// speedup vs baseline: 1.1080x; 1.1080x over previous
#include <cuda_runtime.h>
#include <cuda_fp16.h>

typedef unsigned long long ull;
typedef unsigned int u32;

#define S_LEN  4096
#define HID    2048
#define NH_    16
#define NKV_   4
#define HD_    128
#define KD_KV  512
#define SCALE_ 0.08838834764831845f

// ---------------- scratch (static; no runtime alloc allowed) ----------------
__device__ __half g_hs16[(size_t)S_LEN * HID];
__device__ __half g_wq16[(size_t)HID   * HID];
__device__ __half g_wk16[(size_t)KD_KV * HID];
__device__ __half g_wv16[(size_t)KD_KV * HID];
__device__ __half g_wo16[(size_t)HID   * HID];
__device__ __half g_q16 [(size_t)S_LEN * HID];
__device__ __half g_k16 [(size_t)S_LEN * KD_KV];
__device__ __half g_v16 [(size_t)S_LEN * KD_KV];
__device__ __half g_ao16[(size_t)S_LEN * HID];

// ---------------- helpers ----------------
__device__ __forceinline__ u32 s2u(const void* p) {
    u32 a;
    asm("{ .reg .u64 t; cvta.to.shared.u64 t, %1; cvt.u32.u64 %0, t; }" : "=r"(a) : "l"(p));
    return a;
}
__device__ __forceinline__ u32 sw128(u32 o) { return o ^ ((o >> 3) & 0x70); }
__device__ __forceinline__ void cp16(u32 dst, const void* src) {
    asm volatile("cp.async.cg.shared.global [%0], [%1], 16;" :: "r"(dst), "l"(src));
}
__device__ __forceinline__ void cp_commit() { asm volatile("cp.async.commit_group;" ::: "memory"); }
template<int N> __device__ __forceinline__ void cp_wait() {
    asm volatile("cp.async.wait_group %0;" :: "n"(N) : "memory");
}

__device__ __forceinline__ void ldmx4(u32* r, u32 addr) {
    asm volatile("ldmatrix.sync.aligned.m8n8.x4.shared.b16 {%0,%1,%2,%3}, [%4];"
                 : "=r"(r[0]), "=r"(r[1]), "=r"(r[2]), "=r"(r[3]) : "r"(addr));
}
__device__ __forceinline__ void ldmx4t(u32* r, u32 addr) {
    asm volatile("ldmatrix.sync.aligned.m8n8.x4.trans.shared.b16 {%0,%1,%2,%3}, [%4];"
                 : "=r"(r[0]), "=r"(r[1]), "=r"(r[2]), "=r"(r[3]) : "r"(addr));
}
__device__ __forceinline__ void mma16816h(float* c, const u32* a, u32 b0, u32 b1) {
    asm volatile("mma.sync.aligned.m16n8k16.row.col.f32.f16.f16.f32 "
                 "{%0,%1,%2,%3}, {%4,%5,%6,%7}, {%8,%9}, {%0,%1,%2,%3};"
                 : "+f"(c[0]), "+f"(c[1]), "+f"(c[2]), "+f"(c[3])
                 : "r"(a[0]), "r"(a[1]), "r"(a[2]), "r"(a[3]), "r"(b0), "r"(b1));
}

// ---------------- fused fp32 -> fp16 conversion of all 5 inputs (2-way ILP) ------
#define CVT_N4   4718592
#define CVT_HALF 2359296
__device__ __forceinline__ void cvt_one(int i,
    const float* hs, const float* wq, const float* wk, const float* wv, const float* wo,
    __half* ohs, __half* owq, __half* owk, __half* owv, __half* owo)
{
    const float* src; __half* dst; int off;
    if (i < 2097152)      { src = hs; dst = ohs; off = i; }
    else if (i < 3145728) { src = wq; dst = owq; off = i - 2097152; }
    else if (i < 3407872) { src = wk; dst = owk; off = i - 3145728; }
    else if (i < 3670016) { src = wv; dst = owv; off = i - 3407872; }
    else                  { src = wo; dst = owo; off = i - 3670016; }
    float4 f = ((const float4*)src)[off];
    __half2 h0 = __floats2half2_rn(f.x, f.y);
    __half2 h1 = __floats2half2_rn(f.z, f.w);
    ((uint2*)dst)[off] = make_uint2(*(u32*)&h0, *(u32*)&h1);
}

__global__ __launch_bounds__(256)
void cvt_all(const float* __restrict__ hs, const float* __restrict__ wq,
             const float* __restrict__ wk, const float* __restrict__ wv,
             const float* __restrict__ wo,
             __half* __restrict__ ohs, __half* __restrict__ owq,
             __half* __restrict__ owk, __half* __restrict__ owv,
             __half* __restrict__ owo)
{
    int i = blockIdx.x * 256 + threadIdx.x;
    cvt_one(i,            hs, wq, wk, wv, wo, ohs, owq, owk, owv, owo);
    cvt_one(i + CVT_HALF, hs, wq, wk, wv, wo, ohs, owq, owk, owv, owo);
}

// ---------------- fp16 mma.sync GEMM (R11 config: 128x128, 3-stage, 2 CTA/SM) ----
#define STAGEB 32768
#define NCHUNK 32
#define GEMM_SMEM (3 * STAGEB + 1024)

__device__ __forceinline__ void load_chunk(
    const __half* __restrict__ A, const __half* __restrict__ B,
    int bm, int c, u32 dstA, int tid)
{
    const int ko = c * 64;
    #pragma unroll
    for (int p = 0; p < 8; p++) {
        int u   = tid + p * 256;
        int isB = u >> 10;
        int v   = u & 1023;
        int row = v >> 3, seg = v & 7;
        u32 dst = dstA + (isB ? 16384 : 0) + sw128((u32)(row * 128 + seg * 16));
        const __half* src = isB
            ? B + ((size_t)row) * 2048 + ko + seg * 8
            : A + ((size_t)(bm + row)) * 2048 + ko + seg * 8;
        cp16(dst, src);
    }
    cp_commit();
}

template<bool OUT16>
__device__ __forceinline__ void gemm_core(
    const __half* __restrict__ A, const __half* __restrict__ B,
    void* __restrict__ Cv, int N, int bm, int bn, u32 sbase, int tid)
{
    const int wid = tid >> 5, L = tid & 31;
    const int wm = wid & 3, wn = wid >> 2;     // 4m x 2n warps; warp tile 32x64

    float acc[2][8][4];
    #pragma unroll
    for (int i = 0; i < 2; i++)
        #pragma unroll
        for (int j = 0; j < 8; j++)
            #pragma unroll
            for (int q2 = 0; q2 < 4; q2++) acc[i][j][q2] = 0.f;

    const u32 arow0 = (u32)(wm * 32 + (L & 15));
    const u32 a_sw  = (arow0 & 7) << 4;
    const u32 a_kl  = (u32)(L & 16);
    u32 brow[4], b_sw[4];
    const u32 b_kl = (u32)((L & 8) * 2);
    #pragma unroll
    for (int ng = 0; ng < 4; ng++) {
        brow[ng] = (u32)(wn * 64 + ng * 16 + (L & 7) + ((L & 16) >> 1));
        b_sw[ng] = (brow[ng] & 7) << 4;
    }

    load_chunk(A, B, bm, 0, sbase + 0 * STAGEB, tid);
    load_chunk(A, B, bm, 1, sbase + 1 * STAGEB, tid);
    load_chunk(A, B, bm, 2, sbase + 2 * STAGEB, tid);

    #pragma unroll 1
    for (int c = 0; c < NCHUNK; c++) {
        cp_wait<2>();
        __syncthreads();

        const u32 sA = sbase + (u32)(c % 3) * STAGEB;
        const u32 sB = sA + 16384;
        #pragma unroll
        for (int ks = 0; ks < 4; ks++) {
            const u32 kb2 = (u32)(ks * 32);
            u32 ar[2][4];
            u32 aad = sA + arow0 * 128 + ((kb2 + a_kl) ^ a_sw);
            ldmx4(ar[0], aad);
            ldmx4(ar[1], aad + 2048);
            u32 br[16];
            #pragma unroll
            for (int ng = 0; ng < 4; ng++)
                ldmx4(br + ng * 4, sB + brow[ng] * 128 + ((kb2 + b_kl) ^ b_sw[ng]));
            #pragma unroll
            for (int mf = 0; mf < 2; mf++)
                #pragma unroll
                for (int nf = 0; nf < 8; nf++)
                    mma16816h(acc[mf][nf], ar[mf],
                              br[(nf >> 1) * 4 + (nf & 1) * 2],
                              br[(nf >> 1) * 4 + (nf & 1) * 2 + 1]);
        }

        __syncthreads();
        if (c + 3 < NCHUNK) load_chunk(A, B, bm, c + 3, sA, tid);
        else                cp_commit();
    }

    const int r0   = bm + wm * 32 + (L >> 2);
    const int col0 = bn + wn * 64 + (L & 3) * 2;
    #pragma unroll
    for (int mf = 0; mf < 2; mf++)
        #pragma unroll
        for (int nf = 0; nf < 8; nf++) {
            int r  = r0 + mf * 16;
            int cc = col0 + nf * 8;
            if (OUT16) {
                __half* C = (__half*)Cv;
                *(__half2*)&C[(size_t)r * N + cc] =
                    __floats2half2_rn(acc[mf][nf][0], acc[mf][nf][1]);
                *(__half2*)&C[(size_t)(r + 8) * N + cc] =
                    __floats2half2_rn(acc[mf][nf][2], acc[mf][nf][3]);
            } else {
                float* C = (float*)Cv;
                *(float2*)&C[(size_t)r * N + cc] =
                    make_float2(acc[mf][nf][0], acc[mf][nf][1]);
                *(float2*)&C[(size_t)(r + 8) * N + cc] =
                    make_float2(acc[mf][nf][2], acc[mf][nf][3]);
            }
        }
}

// merged QKV: grid.x = 24 tiles (16 q | 4 k | 4 v), grid.y = 32 m-tiles; fp16 out
__global__ __launch_bounds__(256)
void gemm_qkv(const __half* __restrict__ hs,
              const __half* __restrict__ wq, const __half* __restrict__ wk,
              const __half* __restrict__ wv,
              __half* __restrict__ q, __half* __restrict__ k, __half* __restrict__ v)
{
    extern __shared__ char smraw[];
    const u32 sbase = (s2u(smraw) + 1023) & ~1023u;
    const int nt = blockIdx.x, bm = blockIdx.y * 128;

    const __half* B; __half* C; int N, bn;
    if (nt < 16)      { B = wq + (size_t)nt * 128 * 2048;        C = q; N = HID;   bn = nt * 128; }
    else if (nt < 20) { B = wk + (size_t)(nt - 16) * 128 * 2048; C = k; N = KD_KV; bn = (nt - 16) * 128; }
    else              { B = wv + (size_t)(nt - 20) * 128 * 2048; C = v; N = KD_KV; bn = (nt - 20) * 128; }

    gemm_core<true>(hs, B, C, N, bm, bn, sbase, threadIdx.x);
}

__global__ __launch_bounds__(256)
void gemm_wo(const __half* __restrict__ A, const __half* __restrict__ W,
             float* __restrict__ C)
{
    extern __shared__ char smraw[];
    const u32 sbase = (s2u(smraw) + 1023) & ~1023u;
    const int bn = blockIdx.x * 128, bm = blockIdx.y * 128;
    gemm_core<false>(A, W + (size_t)bn * 2048, C, HID, bm, bn, sbase, threadIdx.x);
}

// ---------------- merged RoPE on q + k (fp16 storage, fp32 math) ----------------
__global__ __launch_bounds__(256)
void rope16_all(__half* __restrict__ q, __half* __restrict__ k,
                const float* __restrict__ cosb, const float* __restrict__ sinb)
{
    int idx = blockIdx.x * blockDim.x + threadIdx.x;
    int d  = idx & 63;
    int hslot = (idx >> 6) % 20;
    int s  = idx / (64 * 20);
    __half* p = (hslot < 16)
        ? q + (size_t)s * HID   + hslot * HD_
        : k + (size_t)s * KD_KV + (hslot - 16) * HD_;
    float x1 = __half2float(p[d]), x2 = __half2float(p[d + 64]);
    float c1 = cosb[s * HD_ + d],      s1 = sinb[s * HD_ + d];
    float c2 = cosb[s * HD_ + d + 64], s2 = sinb[s * HD_ + d + 64];
    p[d]      = __float2half(x1 * c1 - x2 * s1);
    p[d + 64] = __float2half(x2 * c2 + x1 * s2);
}

// ---------------- block-sparse attention: FA2-style, 3-buffer K/V rotation ------
// SMEM: Q 16KB | B0,B1,B2 16KB each = 64KB -> 3 CTAs/SM (12 warps)
#define ATT_SMEM 65536

__device__ __forceinline__ void cp_row_tile(u32 dst, const __half* __restrict__ src,
                                            int rstride, int tid)
{
    #pragma unroll
    for (int p = 0; p < 8; p++) {
        int u = tid + p * 128;
        int r = u >> 4, seg = u & 15;
        u32 ad = dst + (u32)r * 256 + (((u32)(seg * 16)) ^ (((u32)r & 7) << 4));
        cp16(ad, src + (size_t)r * rstride + seg * 8);
    }
    cp_commit();
}

__global__ __launch_bounds__(128, 3)
void attn_kernel(const __half* __restrict__ q, const __half* __restrict__ k,
                 const __half* __restrict__ v, __half* __restrict__ out)
{
    extern __shared__ char smc[];
    const u32 sb = s2u(smc);
    const u32 Qs = sb;
    // K(j) -> buf (2j)%3, V(j) -> buf (2j+1)%3
    #define KBUF(j) (sb + 16384u * (1u + (u32)((2 * (j)) % 3)))
    #define VBUF(j) (sb + 16384u * (1u + (u32)((2 * (j) + 1) % 3)))

    const int t   = blockIdx.x;
    const int h   = blockIdx.y;
    const int kvh = h >> 2;
    const int tid = threadIdx.x;
    const int wid = tid >> 5, L = tid & 31;

    int sel[6]; int ns = 0;
    {
        int lo = t - 4; if (lo < 0) lo = 0;
        int g0 = ((t >> 2) << 2) - 4;
        if (g0 >= 0 && g0 < lo) sel[ns++] = g0;
        for (int b = lo; b <= t; b++) sel[ns++] = b;
    }

    // prologue: Q, K(0), V(0)  (3 cp.async groups)
    cp_row_tile(Qs,      q + (size_t)(t * 64) * HID + h * HD_, HID, tid);
    cp_row_tile(KBUF(0), k + (size_t)(sel[0] * 64) * KD_KV + kvh * HD_, KD_KV, tid);
    cp_row_tile(VBUF(0), v + (size_t)(sel[0] * 64) * KD_KV + kvh * HD_, KD_KV, tid);

    const u32 arow = (u32)(wid * 16 + (L & 15));
    const u32 a_sw = (arow & 7) << 4;
    const u32 a_kl = (u32)(L & 16);
    u32 brow[4], b_sw[4];
    const u32 b_kl = (u32)((L & 8) * 2);
    #pragma unroll
    for (int g = 0; g < 4; g++) {
        brow[g] = (u32)(g * 16 + (L & 7) + ((L & 16) >> 1));
        b_sw[g] = (brow[g] & 7) << 4;
    }
    const u32 vrow = (u32)(L & 15);
    const u32 v_cl = (u32)((L >> 4) * 16);

    const int qrow = wid * 16 + (L >> 2);

    float o[16][4];
    #pragma unroll
    for (int nf = 0; nf < 16; nf++)
        #pragma unroll
        for (int j = 0; j < 4; j++) o[nf][j] = 0.f;
    float lp0 = 0.f, lp1 = 0.f;

    #pragma unroll 1
    for (int jb = 0; jb < ns; jb++) {
        const u32 Kc = KBUF(jb);
        const u32 Vc = VBUF(jb);

        // K(jb) landed (V(jb) may still be in flight); barrier also proves every
        // warp finished PV(jb-1), so K(jb+1) may overwrite V(jb-1)'s buffer.
        cp_wait<1>();
        __syncthreads();
        if (jb + 1 < ns)
            cp_row_tile(KBUF(jb + 1),
                        k + (size_t)(sel[jb + 1] * 64) * KD_KV + kvh * HD_, KD_KV, tid);

        // ---- QK^T ----
        float cs[8][4];
        #pragma unroll
        for (int nf = 0; nf < 8; nf++)
            #pragma unroll
            for (int j = 0; j < 4; j++) cs[nf][j] = 0.f;

        #pragma unroll
        for (int ks = 0; ks < 8; ks++) {
            const u32 kb2 = (u32)(ks * 32);
            u32 ar[4];
            ldmx4(ar, Qs + arow * 256 + ((kb2 + a_kl) ^ a_sw));
            u32 br[16];
            #pragma unroll
            for (int g = 0; g < 4; g++)
                ldmx4(br + g * 4, Kc + brow[g] * 256 + ((kb2 + b_kl) ^ b_sw[g]));
            #pragma unroll
            for (int nf = 0; nf < 8; nf++)
                mma16816h(cs[nf], ar, br[(nf >> 1) * 4 + (nf & 1) * 2],
                                       br[(nf >> 1) * 4 + (nf & 1) * 2 + 1]);
        }

        // ---- exp in registers; build P A-fragments ----
        const bool diag = (sel[jb] == t);
        u32 pf[4][4];
        #pragma unroll
        for (int nf = 0; nf < 8; nf++) {
            int colg = nf * 8 + (L & 3) * 2;
            float e0 = __expf(cs[nf][0] * SCALE_);
            float e1 = __expf(cs[nf][1] * SCALE_);
            float e2 = __expf(cs[nf][2] * SCALE_);
            float e3 = __expf(cs[nf][3] * SCALE_);
            if (diag) {
                if (colg     > qrow)     e0 = 0.f;
                if (colg + 1 > qrow)     e1 = 0.f;
                if (colg     > qrow + 8) e2 = 0.f;
                if (colg + 1 > qrow + 8) e3 = 0.f;
            }
            lp0 += e0 + e1;
            lp1 += e2 + e3;
            __half2 h01 = __floats2half2_rn(e0, e1);
            __half2 h23 = __floats2half2_rn(e2, e3);
            const int kf = nf >> 1;
            if ((nf & 1) == 0) { pf[kf][0] = *(u32*)&h01; pf[kf][1] = *(u32*)&h23; }
            else               { pf[kf][2] = *(u32*)&h01; pf[kf][3] = *(u32*)&h23; }
        }

        // V(jb) landed; barrier proves every warp finished QK(jb), so V(jb+1)
        // may overwrite K(jb)'s buffer.
        if (jb + 1 < ns) cp_wait<1>();
        else             cp_wait<0>();
        __syncthreads();
        if (jb + 1 < ns)
            cp_row_tile(VBUF(jb + 1),
                        v + (size_t)(sel[jb + 1] * 64) * KD_KV + kvh * HD_, KD_KV, tid);

        // ---- P @ V ----
        #pragma unroll
        for (int kf = 0; kf < 4; kf++) {
            #pragma unroll
            for (int dg = 0; dg < 8; dg++) {
                u32 row = (u32)(kf * 16) + vrow;
                u32 cb  = (u32)(dg * 32) + v_cl;
                u32 vr[4];
                ldmx4t(vr, Vc + row * 256 + (cb ^ ((row & 7) << 4)));
                mma16816h(o[dg * 2 + 0], pf[kf], vr[0], vr[1]);
                mma16816h(o[dg * 2 + 1], pf[kf], vr[2], vr[3]);
            }
        }
    }

    lp0 += __shfl_xor_sync(0xFFFFFFFFu, lp0, 1);
    lp0 += __shfl_xor_sync(0xFFFFFFFFu, lp0, 2);
    lp1 += __shfl_xor_sync(0xFFFFFFFFu, lp1, 1);
    lp1 += __shfl_xor_sync(0xFFFFFFFFu, lp1, 2);
    const float il0 = 1.f / lp0, il1 = 1.f / lp1;

    #pragma unroll
    for (int nf = 0; nf < 16; nf++) {
        int col = nf * 8 + (L & 3) * 2;
        __half* o0 = out + (size_t)(t * 64 + qrow) * HID + h * HD_ + col;
        __half* o1 = out + (size_t)(t * 64 + qrow + 8) * HID + h * HD_ + col;
        *(__half2*)o0 = __floats2half2_rn(o[nf][0] * il0, o[nf][1] * il0);
        *(__half2*)o1 = __floats2half2_rn(o[nf][2] * il1, o[nf][3] * il1);
    }
    #undef KBUF
    #undef VBUF
}

// ---------------- launch ----------------
extern "C" void kernel_launch(void* const* d_in, const int* in_sizes, int n_in,
                              void* d_out, int out_size)
{
    const float* hs   = (const float*)d_in[0];
    const float* cosb = (const float*)d_in[1];
    const float* sinb = (const float*)d_in[2];
    const float* wq   = (const float*)d_in[3];
    const float* wk   = (const float*)d_in[4];
    const float* wv   = (const float*)d_in[5];
    const float* wo   = (const float*)d_in[6];
    float* out = (float*)d_out;

    __half *phs, *pwq, *pwk, *pwv, *pwo, *pq16, *pk16, *pv16, *pao16;
    cudaGetSymbolAddress((void**)&phs,   g_hs16);
    cudaGetSymbolAddress((void**)&pwq,   g_wq16);
    cudaGetSymbolAddress((void**)&pwk,   g_wk16);
    cudaGetSymbolAddress((void**)&pwv,   g_wv16);
    cudaGetSymbolAddress((void**)&pwo,   g_wo16);
    cudaGetSymbolAddress((void**)&pq16,  g_q16);
    cudaGetSymbolAddress((void**)&pk16,  g_k16);
    cudaGetSymbolAddress((void**)&pv16,  g_v16);
    cudaGetSymbolAddress((void**)&pao16, g_ao16);

    const dim3 blk(256);

    // fused fp32->fp16 conversion (2 units/thread)
    cvt_all<<<CVT_HALF / 256, blk>>>(hs, wq, wk, wv, wo, phs, pwq, pwk, pwv, pwo);

    cudaFuncSetAttribute(gemm_qkv, cudaFuncAttributeMaxDynamicSharedMemorySize, GEMM_SMEM);
    cudaFuncSetAttribute(gemm_wo,  cudaFuncAttributeMaxDynamicSharedMemorySize, GEMM_SMEM);

    // fused QKV projections -> fp16 (128x128 tiles, 2 CTA/SM)
    gemm_qkv<<<dim3(24, 32), blk, GEMM_SMEM>>>(phs, pwq, pwk, pwv, pq16, pk16, pv16);

    // merged RoPE on q + k
    rope16_all<<<(S_LEN * 20 * 64) / 256, blk>>>(pq16, pk16, cosb, sinb);

    // block-sparse attention (fp16 in/out, 3 CTA/SM)
    cudaFuncSetAttribute(attn_kernel,
                         cudaFuncAttributeMaxDynamicSharedMemorySize, ATT_SMEM);
    attn_kernel<<<dim3(64, NH_), dim3(128), ATT_SMEM>>>(pq16, pk16, pv16, pao16);

    // output projection (fp32 out)
    gemm_wo<<<dim3(16, 32), blk, GEMM_SMEM>>>(pao16, pwo, out);
}